// round 8
// baseline (speedup 1.0000x reference)
#include <cuda_runtime.h>
#include <cuda_fp16.h>
#include <cstdint>

// out[256,64] = haar_dwt2(x[256,262144]) @ W[64,262144]^T + b
// Factorized: out = x @ W'^T + b with W' = adjoint-Haar(W), stored fp16.
// GEMM: mma.sync m16n8k16 fp16 (fp32 accum), split-K 64 x 2 M-tiles.
// A: LDG fp32 (2-iter register lead) -> cvt fp16 -> STS into pitch-80
// 4-slot ring (conflict-free), consumed as fp16 LDS.32 frags.
// B: fp16 pitch-80 rows, 6-stage cp.async ring + ldmatrix (as R6).

#define IN_FEATS (1 << 18)            // 262144
#define BATCH    256
#define NOUT     64
#define KSPLIT   64
#define KC       (IN_FEATS / KSPLIT)  // 4096
#define BK       32
#define NB       (KC / BK)            // 128
#define APITCH   80
#define ASTGB    (128 * APITCH)       // 10240 per A slot
#define ANSTG    4
#define BSTRIDE  80
#define BSTG     (64 * BSTRIDE)       // 5120 per B slot
#define BNSTG    6
#define BBASE    (ANSTG * ASTGB)      // 40960
#define SMEM_ALLOC (BBASE + BNSTG * BSTG)  // 71680

__device__ __half g_Wp[NOUT * IN_FEATS];           // 33.5 MB  W' fp16
__device__ float  g_part[KSPLIT * BATCH * NOUT];   // 4 MB split-K partials

// ---------------- helpers ----------------
__device__ __forceinline__ uint32_t smem_u32(const void* p) {
    uint32_t a;
    asm("{ .reg .u64 t; cvta.to.shared.u64 t, %1; cvt.u32.u64 %0, t; }"
        : "=r"(a) : "l"(p));
    return a;
}
__device__ __forceinline__ void cp_async16(uint32_t dst, const void* src) {
    asm volatile("cp.async.cg.shared.global [%0], [%1], 16;"
                 :: "r"(dst), "l"(src) : "memory");
}
__device__ __forceinline__ void cp_commit() {
    asm volatile("cp.async.commit_group;" ::: "memory");
}
template <int N>
__device__ __forceinline__ void cp_wait() {
    asm volatile("cp.async.wait_group %0;" :: "n"(N) : "memory");
}
__device__ __forceinline__ void mma_fp16(float* d, const uint32_t* a,
                                         const uint32_t* b) {
    asm volatile(
        "mma.sync.aligned.m16n8k16.row.col.f32.f16.f16.f32 "
        "{%0,%1,%2,%3}, {%4,%5,%6,%7}, {%8,%9}, {%0,%1,%2,%3};"
        : "+f"(d[0]), "+f"(d[1]), "+f"(d[2]), "+f"(d[3])
        : "r"(a[0]), "r"(a[1]), "r"(a[2]), "r"(a[3]), "r"(b[0]), "r"(b[1]));
}
#define LDMX4(r0, r1, r2, r3, addr)                                          \
    asm volatile("ldmatrix.sync.aligned.m8n8.x4.shared.b16 {%0,%1,%2,%3}, [%4];" \
                 : "=r"(r0), "=r"(r1), "=r"(r2), "=r"(r3) : "r"(addr))
__device__ __forceinline__ uint32_t h2u(__half2 h) { return *(uint32_t*)&h; }

// ---------- Kernel 1: W' = adjoint-DWT(W), fp16, 8 outputs/thread ----------
__global__ __launch_bounds__(256) void k_wtransform(const float* __restrict__ W) {
    int t   = blockIdx.x * 256 + threadIdx.x;
    int idx = t << 3;
    int n    = idx >> 18;
    int rem  = idx & (IN_FEATS - 1);
    int c    = rem >> 16;
    int r    = (rem >> 8) & 255;
    int colb = rem & 255;
    int p = r >> 1, q0 = colb >> 1;

    const float* base = W + ((size_t)n << 18) + (c << 16) + (p << 7) + q0;
    float4 LL = *(const float4*)(base);
    float4 LH = *(const float4*)(base + 16384);
    float4 HL = *(const float4*)(base + 32768);
    float4 HH = *(const float4*)(base + 49152);

    float rs = (r & 1) ? -1.0f : 1.0f;
    float e0 = LL.x + rs * LH.x, f0 = HL.x + rs * HH.x;
    float e1 = LL.y + rs * LH.y, f1 = HL.y + rs * HH.y;
    float e2 = LL.z + rs * LH.z, f2 = HL.z + rs * HH.z;
    float e3 = LL.w + rs * LH.w, f3 = HL.w + rs * HH.w;

    uint4 o;
    o.x = h2u(__floats2half2_rn(0.5f * (e0 + f0), 0.5f * (e0 - f0)));
    o.y = h2u(__floats2half2_rn(0.5f * (e1 + f1), 0.5f * (e1 - f1)));
    o.z = h2u(__floats2half2_rn(0.5f * (e2 + f2), 0.5f * (e2 - f2)));
    o.w = h2u(__floats2half2_rn(0.5f * (e3 + f3), 0.5f * (e3 - f3)));
    *(uint4*)(g_Wp + idx) = o;
}

// ---------- Kernel 2: mma.sync fp16 split-K GEMM ----------
// Grid (64, 2). CTA 512 thr = 16 warps, warp tile 16(m) x 32(n).
__global__ __launch_bounds__(512, 1) void k_gemm_mma(const float* __restrict__ x) {
    extern __shared__ __align__(128) char sm[];
    uint32_t sb = smem_u32(sm);
    int tid = threadIdx.x, l = tid & 31, wid = tid >> 5;
    int ks = blockIdx.x, mt = blockIdx.y;
    int wm = wid >> 1, wn = wid & 1;

    // ---- A staging: thread -> row tid>>2, k-seg tid&3 (8 floats) ----
    int tr = tid >> 2, seg = tid & 3;
    const float* a_src = x + (size_t)(mt * 128 + tr) * IN_FEATS
                           + (size_t)ks * KC + seg * 8;
    uint32_t a_sts = sb + (uint32_t)tr * APITCH + seg * 16;

    // ---- B staging: tid<256: row tid>>2, 16B chunk tid&3 ----
    int brow = (tid & 255) >> 2, bc = tid & 3;
    const __half* b_src = g_Wp + (size_t)brow * IN_FEATS + (size_t)ks * KC + bc * 8;
    uint32_t b_dst = sb + BBASE + (uint32_t)brow * BSTRIDE + bc * 16;
    bool has_b = (tid < 256);

    // ---- fragment read bases ----
    int r0 = wm * 16 + (l >> 2), q = (l & 3) * 2;
    uint32_t a_rd = sb + (uint32_t)r0 * APITCH + q * 2;
    uint32_t lm_base = sb + BBASE
                     + (uint32_t)(wn * 32 + (l & 7) + ((l >> 4) & 1) * 8) * BSTRIDE
                     + (((l >> 3) & 1) << 4);

    float acc[4][4];
#pragma unroll
    for (int f = 0; f < 4; f++)
#pragma unroll
        for (int i = 0; i < 4; i++) acc[f][i] = 0.0f;

    float4 rb[2][2];
#define LDGA(j, buf)                                                        \
    do {                                                                    \
        rb[buf][0] = *(const float4*)(a_src + (j) * BK);                    \
        rb[buf][1] = *(const float4*)(a_src + (j) * BK + 4);                \
    } while (0)
#define STSA(buf, slot)                                                    \
    do {                                                                   \
        uint32_t c0 = h2u(__floats2half2_rn(rb[buf][0].x, rb[buf][0].y));  \
        uint32_t c1 = h2u(__floats2half2_rn(rb[buf][0].z, rb[buf][0].w));  \
        uint32_t c2 = h2u(__floats2half2_rn(rb[buf][1].x, rb[buf][1].y));  \
        uint32_t c3 = h2u(__floats2half2_rn(rb[buf][1].z, rb[buf][1].w));  \
        asm volatile("st.shared.v4.b32 [%0], {%1,%2,%3,%4};"               \
                     :: "r"(a_sts + (uint32_t)(slot) * ASTGB),             \
                        "r"(c0), "r"(c1), "r"(c2), "r"(c3));               \
    } while (0)

    // prologue: A kblk 0,1 staged; regs hold kblk 2,3; B stages 0..4
    LDGA(0, 0); LDGA(1, 1);
    STSA(0, 0); LDGA(2, 0);
    STSA(1, 1); LDGA(3, 1);
#pragma unroll
    for (int s = 0; s < BNSTG - 1; s++) {
        if (has_b) cp_async16(b_dst + s * BSTG, b_src + s * BK);
        cp_commit();
    }

    for (int jb = 0; jb < NB; jb++) {
        cp_wait<BNSTG - 2>();
        __syncthreads();

        // A: stage kblk jb+2, then fetch kblk jb+4 into regs
        STSA(jb & 1, (jb + 2) & (ANSTG - 1));
        if (jb + 4 < NB) LDGA(jb + 4, jb & 1);

        // B: refill slot (jb+5)%6 with kblk jb+5
        if (jb + BNSTG - 1 < NB && has_b)
            cp_async16(b_dst + ((jb + BNSTG - 1) % BNSTG) * BSTG,
                       b_src + (jb + BNSTG - 1) * BK);
        cp_commit();

        uint32_t sA = (uint32_t)(jb & (ANSTG - 1)) * ASTGB;
        uint32_t sB = (uint32_t)(jb % BNSTG) * BSTG;
#pragma unroll
        for (int k0 = 0; k0 < 2; k0++) {
            // A frags (fp16): [r0,q], [r0+8,q], [r0,q+8], [r0+8,q+8] @ k0*16 cols
            uint32_t ah[4];
            uint32_t ab = a_rd + sA + k0 * 32;
            asm volatile("ld.shared.b32 %0, [%1];"       : "=r"(ah[0]) : "r"(ab));
            asm volatile("ld.shared.b32 %0, [%1 + 640];" : "=r"(ah[1]) : "r"(ab));
            asm volatile("ld.shared.b32 %0, [%1 + 16];"  : "=r"(ah[2]) : "r"(ab));
            asm volatile("ld.shared.b32 %0, [%1 + 656];" : "=r"(ah[3]) : "r"(ab));
#pragma unroll
            for (int fp = 0; fp < 2; fp++) {
                uint32_t b0, b1, b2, b3;
                LDMX4(b0, b1, b2, b3, lm_base + sB + fp * (16 * BSTRIDE) + k0 * 32);
                uint32_t bf0[2] = {b0, b1}, bf1[2] = {b2, b3};
                mma_fp16(acc[fp * 2],     ah, bf0);
                mma_fp16(acc[fp * 2 + 1], ah, bf1);
            }
        }
    }

    // epilogue: split-K partials
    int gm0 = mt * 128 + r0;
    float* pbase = g_part + ((size_t)ks * BATCH + gm0) * NOUT;
#pragma unroll
    for (int f = 0; f < 4; f++) {
        int n = wn * 32 + f * 8 + q;
        *(float2*)(pbase + n)            = make_float2(acc[f][0], acc[f][1]);
        *(float2*)(pbase + 8 * NOUT + n) = make_float2(acc[f][2], acc[f][3]);
    }
}

// ---------- Kernel 3: reduce split-K partials + bias ----------
__global__ __launch_bounds__(256) void k_reduce(const float* __restrict__ bias,
                                                float* __restrict__ out) {
    int t = blockIdx.x * 256 + threadIdx.x;     // 0..16383
    float s = bias[t & (NOUT - 1)];
    const float* p = g_part + t;
#pragma unroll 16
    for (int ks = 0; ks < KSPLIT; ks++)
        s += p[(size_t)ks * BATCH * NOUT];
    out[t] = s;
}

extern "C" void kernel_launch(void* const* d_in, const int* in_sizes, int n_in,
                              void* d_out, int out_size) {
    const float* x = (const float*)d_in[0];
    const float* W = (const float*)d_in[1];
    const float* b = (const float*)d_in[2];

    cudaFuncSetAttribute(k_gemm_mma, cudaFuncAttributeMaxDynamicSharedMemorySize,
                         SMEM_ALLOC);

    k_wtransform<<<(NOUT * IN_FEATS / 8) / 256, 256>>>(W);
    k_gemm_mma<<<dim3(KSPLIT, BATCH / 128), 512, SMEM_ALLOC>>>(x);
    k_reduce<<<(BATCH * NOUT) / 256, 256>>>(b, (float*)d_out);
}

// round 9
// speedup vs baseline: 1.0739x; 1.0739x over previous
#include <cuda_runtime.h>
#include <cuda_fp16.h>
#include <cstdint>

// out[256,64] = haar_dwt2(x[256,262144]) @ W[64,262144]^T + b
// Factorized: out = x @ W'^T + b with W' = adjoint-Haar(W), stored fp16.
// GEMM: mma.sync m16n8k16 fp16 (fp32 accum), split-K 74 x 2 M-tiles
// (148 CTAs = every SM, one wave, occ 1). A staged fp32 + XOR swizzle,
// B fp16 pitch-80 + ldmatrix, 6-stage cp.async ring, 512 thr.  (R6 skeleton)

#define IN_FEATS (1 << 18)            // 262144
#define BATCH    256
#define NOUT     64
#define KSPLIT   74
#define NBT      8192                 // total k-blocks
#define BK       32
#define ASTG     16384                // A stage: 128 rows x 128 B
#define BSTRIDE  80
#define BSTG     (64 * BSTRIDE)       // 5120
#define STG      (ASTG + BSTG)        // 21504
#define NSTG     6
#define SMEM_ALLOC (NSTG * STG)       // 129024

__device__ __half g_Wp[NOUT * IN_FEATS];           // 33.5 MB  W' fp16
__device__ float  g_part[KSPLIT * BATCH * NOUT];   // 4.85 MB split-K partials

// ---------------- helpers ----------------
__device__ __forceinline__ uint32_t smem_u32(const void* p) {
    uint32_t a;
    asm("{ .reg .u64 t; cvta.to.shared.u64 t, %1; cvt.u32.u64 %0, t; }"
        : "=r"(a) : "l"(p));
    return a;
}
__device__ __forceinline__ void cp_async16(uint32_t dst, const void* src) {
    asm volatile("cp.async.cg.shared.global [%0], [%1], 16;"
                 :: "r"(dst), "l"(src) : "memory");
}
__device__ __forceinline__ void cp_commit() {
    asm volatile("cp.async.commit_group;" ::: "memory");
}
template <int N>
__device__ __forceinline__ void cp_wait() {
    asm volatile("cp.async.wait_group %0;" :: "n"(N) : "memory");
}
__device__ __forceinline__ void mma_fp16(float* d, const uint32_t* a,
                                         const uint32_t* b) {
    asm volatile(
        "mma.sync.aligned.m16n8k16.row.col.f32.f16.f16.f32 "
        "{%0,%1,%2,%3}, {%4,%5,%6,%7}, {%8,%9}, {%0,%1,%2,%3};"
        : "+f"(d[0]), "+f"(d[1]), "+f"(d[2]), "+f"(d[3])
        : "r"(a[0]), "r"(a[1]), "r"(a[2]), "r"(a[3]), "r"(b[0]), "r"(b[1]));
}
#define LDMX4(r0, r1, r2, r3, addr)                                          \
    asm volatile("ldmatrix.sync.aligned.m8n8.x4.shared.b16 {%0,%1,%2,%3}, [%4];" \
                 : "=r"(r0), "=r"(r1), "=r"(r2), "=r"(r3) : "r"(addr))
__device__ __forceinline__ uint32_t h2u(__half2 h) { return *(uint32_t*)&h; }

// ---------- Kernel 1: W' = adjoint-DWT(W), fp16, 8 outputs/thread ----------
__global__ __launch_bounds__(256) void k_wtransform(const float* __restrict__ W) {
    int t   = blockIdx.x * 256 + threadIdx.x;
    int idx = t << 3;
    int n    = idx >> 18;
    int rem  = idx & (IN_FEATS - 1);
    int c    = rem >> 16;
    int r    = (rem >> 8) & 255;
    int colb = rem & 255;
    int p = r >> 1, q0 = colb >> 1;

    const float* base = W + ((size_t)n << 18) + (c << 16) + (p << 7) + q0;
    float4 LL = *(const float4*)(base);
    float4 LH = *(const float4*)(base + 16384);
    float4 HL = *(const float4*)(base + 32768);
    float4 HH = *(const float4*)(base + 49152);

    float rs = (r & 1) ? -1.0f : 1.0f;
    float e0 = LL.x + rs * LH.x, f0 = HL.x + rs * HH.x;
    float e1 = LL.y + rs * LH.y, f1 = HL.y + rs * HH.y;
    float e2 = LL.z + rs * LH.z, f2 = HL.z + rs * HH.z;
    float e3 = LL.w + rs * LH.w, f3 = HL.w + rs * HH.w;

    uint4 o;
    o.x = h2u(__floats2half2_rn(0.5f * (e0 + f0), 0.5f * (e0 - f0)));
    o.y = h2u(__floats2half2_rn(0.5f * (e1 + f1), 0.5f * (e1 - f1)));
    o.z = h2u(__floats2half2_rn(0.5f * (e2 + f2), 0.5f * (e2 - f2)));
    o.w = h2u(__floats2half2_rn(0.5f * (e3 + f3), 0.5f * (e3 - f3)));
    *(uint4*)(g_Wp + idx) = o;
}

// ---------- Kernel 2: mma.sync fp16 split-K GEMM ----------
// Grid (74, 2). CTA 512 thr = 16 warps, warp tile 16(m) x 32(n).
// k-blocks: 8192 = 52*111 + 22*110.
__global__ __launch_bounds__(512, 1) void k_gemm_mma(const float* __restrict__ x) {
    extern __shared__ __align__(128) char sm[];
    uint32_t sb = smem_u32(sm);
    int tid = threadIdx.x, l = tid & 31, wid = tid >> 5;
    int ks = blockIdx.x, mt = blockIdx.y;
    int wm = wid >> 1, wn = wid & 1;

    int nb  = 110 + (ks < 52 ? 1 : 0);
    int jb0 = ks * 110 + (ks < 52 ? ks : 52);
    size_t k0off = (size_t)jb0 * BK;

    // ---- A staging: slot tid: row=tid>>3, chunk c=tid&7, + row 64 ----
    int arow = tid >> 3, ac = tid & 7;
    const float* a_src0 = x + (size_t)(mt * 128 + arow) * IN_FEATS + k0off + ac * 4;
    const float* a_src1 = a_src0 + (size_t)64 * IN_FEATS;
    uint32_t swz = (uint32_t)(ac ^ (arow & 7)) << 4;
    uint32_t a_dst0 = sb + (uint32_t)arow * 128 + swz;
    uint32_t a_dst1 = a_dst0 + 64 * 128;

    // ---- B staging: tid<256: row tid>>2, 16B chunk tid&3 ----
    int brow = (tid & 255) >> 2, bc = tid & 3;
    const __half* b_src = g_Wp + (size_t)brow * IN_FEATS + k0off + bc * 8;
    uint32_t b_dst = sb + ASTG + (uint32_t)brow * BSTRIDE + bc * 16;
    bool has_b = (tid < 256);

    // ---- fragment read bases ----
    int r0 = wm * 16 + (l >> 2), q = (l & 3) * 2;
    int cb = (l >> 1) & 1, rw = r0 & 7;
    uint32_t arb = sb + (uint32_t)r0 * 128 + (l & 1) * 8;
    uint32_t lm_base = sb + ASTG
                     + (uint32_t)(wn * 32 + (l & 7) + ((l >> 4) & 1) * 8) * BSTRIDE
                     + (((l >> 3) & 1) << 4);

    float acc[4][4];
#pragma unroll
    for (int f = 0; f < 4; f++)
#pragma unroll
        for (int i = 0; i < 4; i++) acc[f][i] = 0.0f;

#define ISSUE_CP(jb, so)                                                    \
    do {                                                                    \
        int ko_ = (jb) * BK;                                                \
        cp_async16(a_dst0 + (so), a_src0 + ko_);                            \
        cp_async16(a_dst1 + (so), a_src1 + ko_);                            \
        if (has_b) cp_async16(b_dst + (so), b_src + ko_);                   \
    } while (0)

    // prologue: stages 0..NSTG-2 (nb >= 110 >> NSTG)
#pragma unroll
    for (int s = 0; s < NSTG - 1; s++) {
        ISSUE_CP(s, (uint32_t)s * STG);
        cp_commit();
    }

    uint32_t cur = 0, pre = (NSTG - 1) * STG;
    for (int jb = 0; jb < nb; jb++) {
        cp_wait<NSTG - 2>();
        __syncthreads();

        if (jb + NSTG - 1 < nb) ISSUE_CP(jb + NSTG - 1, pre);
        cp_commit();

#pragma unroll
        for (int k0 = 0; k0 < 2; k0++) {
            uint32_t ah[4];
            uint32_t c0 = (uint32_t)((cb + 4 * k0) ^ rw) << 4;
            uint32_t c1 = (uint32_t)((cb + 4 * k0 + 2) ^ rw) << 4;
#pragma unroll
            for (int i = 0; i < 4; i++) {
                uint32_t addr = arb + cur + ((i & 1) ? 1024u : 0u)
                              + ((i & 2) ? c1 : c0);
                float2 v;
                asm volatile("ld.shared.v2.f32 {%0,%1}, [%2];"
                             : "=f"(v.x), "=f"(v.y) : "r"(addr));
                ah[i] = h2u(__floats2half2_rn(v.x, v.y));
            }
#pragma unroll
            for (int fp = 0; fp < 2; fp++) {
                uint32_t b0, b1, b2, b3;
                LDMX4(b0, b1, b2, b3, lm_base + cur + fp * (16 * BSTRIDE) + k0 * 32);
                uint32_t bf0[2] = {b0, b1}, bf1[2] = {b2, b3};
                mma_fp16(acc[fp * 2],     ah, bf0);
                mma_fp16(acc[fp * 2 + 1], ah, bf1);
            }
        }

        cur += STG; if (cur == NSTG * STG) cur = 0;
        pre += STG; if (pre == NSTG * STG) pre = 0;
    }

    // epilogue: split-K partials
    int gm0 = mt * 128 + r0;
    float* pbase = g_part + ((size_t)ks * BATCH + gm0) * NOUT;
#pragma unroll
    for (int f = 0; f < 4; f++) {
        int n = wn * 32 + f * 8 + q;
        *(float2*)(pbase + n)            = make_float2(acc[f][0], acc[f][1]);
        *(float2*)(pbase + 8 * NOUT + n) = make_float2(acc[f][2], acc[f][3]);
    }
}

// ---------- Kernel 3: reduce split-K partials + bias ----------
__global__ __launch_bounds__(256) void k_reduce(const float* __restrict__ bias,
                                                float* __restrict__ out) {
    int t = blockIdx.x * 256 + threadIdx.x;     // 0..16383
    float s = bias[t & (NOUT - 1)];
    const float* p = g_part + t;
#pragma unroll 2
    for (int ks = 0; ks < KSPLIT; ks++)
        s += p[(size_t)ks * BATCH * NOUT];
    out[t] = s;
}

extern "C" void kernel_launch(void* const* d_in, const int* in_sizes, int n_in,
                              void* d_out, int out_size) {
    const float* x = (const float*)d_in[0];
    const float* W = (const float*)d_in[1];
    const float* b = (const float*)d_in[2];

    cudaFuncSetAttribute(k_gemm_mma, cudaFuncAttributeMaxDynamicSharedMemorySize,
                         SMEM_ALLOC);

    k_wtransform<<<(NOUT * IN_FEATS / 8) / 256, 256>>>(W);
    k_gemm_mma<<<dim3(KSPLIT, BATCH / 128), 512, SMEM_ALLOC>>>(x);
    k_reduce<<<(BATCH * NOUT) / 256, 256>>>(b, (float*)d_out);
}

// round 10
// speedup vs baseline: 1.1064x; 1.0302x over previous
#include <cuda_runtime.h>
#include <cuda_fp16.h>
#include <cstdint>

// out[256,64] = haar_dwt2(x[256,262144]) @ W[64,262144]^T + b
// Factorized: out = x @ W'^T + b with W' = adjoint-Haar(W), stored fp16.
// GEMM: mma.sync m16n8k16 fp16 (fp32 accum), split-K 74 x 2 M-tiles.
// k-block = 64 cols: each ring stage = 2 proven 32-col half-stages
// (A fp32 + XOR swizzle; B fp16 pitch-80 + ldmatrix). 3-stage cp.async
// ring (43 KB/stage), 512 thr, occ 1.

#define IN_FEATS (1 << 18)            // 262144
#define BATCH    256
#define NOUT     64
#define KSPLIT   74
#define BK       64                   // fp32 cols per k-block (2 halves of 32)
#define NBT      (IN_FEATS / BK)      // 4096 total k-blocks
#define ASTG     16384                // A half-stage: 128 rows x 128 B
#define BSTRIDE  80
#define BSTG     (64 * BSTRIDE)       // 5120
#define HSTG     (ASTG + BSTG)        // 21504 (one 32-col half)
#define STG      (2 * HSTG)           // 43008 (one 64-col stage)
#define NSTG     3
#define SMEM_ALLOC (NSTG * STG)       // 129024

__device__ __half g_Wp[NOUT * IN_FEATS];           // 33.5 MB  W' fp16
__device__ float  g_part[KSPLIT * BATCH * NOUT];   // 4.85 MB split-K partials

// ---------------- helpers ----------------
__device__ __forceinline__ uint32_t smem_u32(const void* p) {
    uint32_t a;
    asm("{ .reg .u64 t; cvta.to.shared.u64 t, %1; cvt.u32.u64 %0, t; }"
        : "=r"(a) : "l"(p));
    return a;
}
__device__ __forceinline__ void cp_async16(uint32_t dst, const void* src) {
    asm volatile("cp.async.cg.shared.global [%0], [%1], 16;"
                 :: "r"(dst), "l"(src) : "memory");
}
__device__ __forceinline__ void cp_commit() {
    asm volatile("cp.async.commit_group;" ::: "memory");
}
template <int N>
__device__ __forceinline__ void cp_wait() {
    asm volatile("cp.async.wait_group %0;" :: "n"(N) : "memory");
}
__device__ __forceinline__ void mma_fp16(float* d, const uint32_t* a,
                                         const uint32_t* b) {
    asm volatile(
        "mma.sync.aligned.m16n8k16.row.col.f32.f16.f16.f32 "
        "{%0,%1,%2,%3}, {%4,%5,%6,%7}, {%8,%9}, {%0,%1,%2,%3};"
        : "+f"(d[0]), "+f"(d[1]), "+f"(d[2]), "+f"(d[3])
        : "r"(a[0]), "r"(a[1]), "r"(a[2]), "r"(a[3]), "r"(b[0]), "r"(b[1]));
}
#define LDMX4(r0, r1, r2, r3, addr)                                          \
    asm volatile("ldmatrix.sync.aligned.m8n8.x4.shared.b16 {%0,%1,%2,%3}, [%4];" \
                 : "=r"(r0), "=r"(r1), "=r"(r2), "=r"(r3) : "r"(addr))
__device__ __forceinline__ uint32_t h2u(__half2 h) { return *(uint32_t*)&h; }

// ---------- Kernel 1: W' = adjoint-DWT(W), fp16, 8 outputs/thread ----------
__global__ __launch_bounds__(256) void k_wtransform(const float* __restrict__ W) {
    int t   = blockIdx.x * 256 + threadIdx.x;
    int idx = t << 3;
    int n    = idx >> 18;
    int rem  = idx & (IN_FEATS - 1);
    int c    = rem >> 16;
    int r    = (rem >> 8) & 255;
    int colb = rem & 255;
    int p = r >> 1, q0 = colb >> 1;

    const float* base = W + ((size_t)n << 18) + (c << 16) + (p << 7) + q0;
    float4 LL = *(const float4*)(base);
    float4 LH = *(const float4*)(base + 16384);
    float4 HL = *(const float4*)(base + 32768);
    float4 HH = *(const float4*)(base + 49152);

    float rs = (r & 1) ? -1.0f : 1.0f;
    float e0 = LL.x + rs * LH.x, f0 = HL.x + rs * HH.x;
    float e1 = LL.y + rs * LH.y, f1 = HL.y + rs * HH.y;
    float e2 = LL.z + rs * LH.z, f2 = HL.z + rs * HH.z;
    float e3 = LL.w + rs * LH.w, f3 = HL.w + rs * HH.w;

    uint4 o;
    o.x = h2u(__floats2half2_rn(0.5f * (e0 + f0), 0.5f * (e0 - f0)));
    o.y = h2u(__floats2half2_rn(0.5f * (e1 + f1), 0.5f * (e1 - f1)));
    o.z = h2u(__floats2half2_rn(0.5f * (e2 + f2), 0.5f * (e2 - f2)));
    o.w = h2u(__floats2half2_rn(0.5f * (e3 + f3), 0.5f * (e3 - f3)));
    *(uint4*)(g_Wp + idx) = o;
}

// ---------- Kernel 2: mma.sync fp16 split-K GEMM ----------
// Grid (74, 2). CTA 512 thr = 16 warps, warp tile 16(m) x 32(n).
// 64-col k-blocks: 4096 = 26*56 + 48*55.
__global__ __launch_bounds__(512, 1) void k_gemm_mma(const float* __restrict__ x) {
    extern __shared__ __align__(128) char sm[];
    uint32_t sb = smem_u32(sm);
    int tid = threadIdx.x, l = tid & 31, wid = tid >> 5;
    int ks = blockIdx.x, mt = blockIdx.y;
    int wm = wid >> 1, wn = wid & 1;

    int nb  = 55 + (ks < 26 ? 1 : 0);
    int jb0 = ks * 55 + (ks < 26 ? ks : 26);
    size_t k0off = (size_t)jb0 * BK;

    // ---- A staging (per 32-col half): row=tid>>3, chunk=tid&7, + row 64 ----
    int arow = tid >> 3, ac = tid & 7;
    const float* a_src0 = x + (size_t)(mt * 128 + arow) * IN_FEATS + k0off + ac * 4;
    const float* a_src1 = a_src0 + (size_t)64 * IN_FEATS;
    uint32_t swz = (uint32_t)(ac ^ (arow & 7)) << 4;
    uint32_t a_dst0 = sb + (uint32_t)arow * 128 + swz;
    uint32_t a_dst1 = a_dst0 + 64 * 128;

    // ---- B staging (per half): tid<256: row tid>>2, 16B chunk tid&3 ----
    int brow = (tid & 255) >> 2, bc = tid & 3;
    const __half* b_src = g_Wp + (size_t)brow * IN_FEATS + k0off + bc * 8;
    uint32_t b_dst = sb + ASTG + (uint32_t)brow * BSTRIDE + bc * 16;
    bool has_b = (tid < 256);

    // ---- fragment read bases ----
    int r0 = wm * 16 + (l >> 2), q = (l & 3) * 2;
    int cb = (l >> 1) & 1, rw = r0 & 7;
    uint32_t arb = sb + (uint32_t)r0 * 128 + (l & 1) * 8;
    uint32_t lm_base = sb + ASTG
                     + (uint32_t)(wn * 32 + (l & 7) + ((l >> 4) & 1) * 8) * BSTRIDE
                     + (((l >> 3) & 1) << 4);

    float acc[4][4];
#pragma unroll
    for (int f = 0; f < 4; f++)
#pragma unroll
        for (int i = 0; i < 4; i++) acc[f][i] = 0.0f;

#define ISSUE_CP(jb, so)                                                    \
    do {                                                                    \
        _Pragma("unroll")                                                   \
        for (int h_ = 0; h_ < 2; h_++) {                                    \
            int ko_ = (jb) * BK + h_ * 32;                                  \
            uint32_t ho_ = (so) + (uint32_t)h_ * HSTG;                      \
            cp_async16(a_dst0 + ho_, a_src0 + ko_);                         \
            cp_async16(a_dst1 + ho_, a_src1 + ko_);                         \
            if (has_b) cp_async16(b_dst + ho_, b_src + ko_);                \
        }                                                                   \
    } while (0)

    // prologue: stages 0..NSTG-2
#pragma unroll
    for (int s = 0; s < NSTG - 1; s++) {
        ISSUE_CP(s, (uint32_t)s * STG);
        cp_commit();
    }

    uint32_t cur = 0, pre = (NSTG - 1) * STG;
    for (int jb = 0; jb < nb; jb++) {
        cp_wait<NSTG - 2>();
        __syncthreads();

        if (jb + NSTG - 1 < nb) ISSUE_CP(jb + NSTG - 1, pre);
        cp_commit();

#pragma unroll
        for (int h = 0; h < 2; h++) {
            uint32_t hb = cur + (uint32_t)h * HSTG;
#pragma unroll
            for (int k0 = 0; k0 < 2; k0++) {
                uint32_t ah[4];
                uint32_t c0 = (uint32_t)((cb + 4 * k0) ^ rw) << 4;
                uint32_t c1 = (uint32_t)((cb + 4 * k0 + 2) ^ rw) << 4;
#pragma unroll
                for (int i = 0; i < 4; i++) {
                    uint32_t addr = arb + hb + ((i & 1) ? 1024u : 0u)
                                  + ((i & 2) ? c1 : c0);
                    float2 v;
                    asm volatile("ld.shared.v2.f32 {%0,%1}, [%2];"
                                 : "=f"(v.x), "=f"(v.y) : "r"(addr));
                    ah[i] = h2u(__floats2half2_rn(v.x, v.y));
                }
#pragma unroll
                for (int fp = 0; fp < 2; fp++) {
                    uint32_t b0, b1, b2, b3;
                    LDMX4(b0, b1, b2, b3,
                          lm_base + hb + fp * (16 * BSTRIDE) + k0 * 32);
                    uint32_t bf0[2] = {b0, b1}, bf1[2] = {b2, b3};
                    mma_fp16(acc[fp * 2],     ah, bf0);
                    mma_fp16(acc[fp * 2 + 1], ah, bf1);
                }
            }
        }

        cur += STG; if (cur == NSTG * STG) cur = 0;
        pre += STG; if (pre == NSTG * STG) pre = 0;
    }

    // epilogue: split-K partials
    int gm0 = mt * 128 + r0;
    float* pbase = g_part + ((size_t)ks * BATCH + gm0) * NOUT;
#pragma unroll
    for (int f = 0; f < 4; f++) {
        int n = wn * 32 + f * 8 + q;
        *(float2*)(pbase + n)            = make_float2(acc[f][0], acc[f][1]);
        *(float2*)(pbase + 8 * NOUT + n) = make_float2(acc[f][2], acc[f][3]);
    }
}

// ---------- Kernel 3: reduce split-K partials + bias ----------
__global__ __launch_bounds__(256) void k_reduce(const float* __restrict__ bias,
                                                float* __restrict__ out) {
    int t = blockIdx.x * 256 + threadIdx.x;     // 0..16383
    float s = bias[t & (NOUT - 1)];
    const float* p = g_part + t;
#pragma unroll 2
    for (int ks = 0; ks < KSPLIT; ks++)
        s += p[(size_t)ks * BATCH * NOUT];
    out[t] = s;
}

extern "C" void kernel_launch(void* const* d_in, const int* in_sizes, int n_in,
                              void* d_out, int out_size) {
    const float* x = (const float*)d_in[0];
    const float* W = (const float*)d_in[1];
    const float* b = (const float*)d_in[2];

    cudaFuncSetAttribute(k_gemm_mma, cudaFuncAttributeMaxDynamicSharedMemorySize,
                         SMEM_ALLOC);

    k_wtransform<<<(NOUT * IN_FEATS / 8) / 256, 256>>>(W);
    k_gemm_mma<<<dim3(KSPLIT, BATCH / 128), 512, SMEM_ALLOC>>>(x);
    k_reduce<<<(BATCH * NOUT) / 256, 256>>>(b, (float*)d_out);
}